// round 16
// baseline (speedup 1.0000x reference)
#include <cuda_runtime.h>
#include <math.h>

#define BB 32768
#define EE 9
#define RANKK 50
#define DD 450            // E*RANK
#define WPB 8             // warps per block
#define NB 740            // persistent grid: 148 SMs x 5 blocks
#define NBP 768           // padded partial stride (pad slots stay zero)
#define TOTW (NB * WPB)   // 5920 warps
#define XOFF 2            // head starts at sxw[2] so rel (sxw[452]) is 16B-aligned
#define XSZ 1352          // 2 + 450 + 900

// per-block partials: [v*NBP + block], v = 0..8 load, 9..17 importance
__device__ float g_part[18 * NBP];
__device__ unsigned int g_count = 0;

__device__ __forceinline__ float softplusf(float x) {
    if (x > 20.0f) return x;
    return log1pf(expf(x));
}
__device__ __forceinline__ float phif(float z) {
    return 0.5f * (1.0f + erff(z * 0.70710678118654752f));
}
__device__ __forceinline__ void cp_async8(unsigned int dst, const void* src) {
    asm volatile("cp.async.ca.shared.global [%0], [%1], 8;" :: "r"(dst), "l"(src));
}
__device__ __forceinline__ void cp_async16(unsigned int dst, const void* src) {
    asm volatile("cp.async.ca.shared.global [%0], [%1], 16;" :: "r"(dst), "l"(src));
}
__device__ __forceinline__ void cp_async_wait_all() {
    asm volatile("cp.async.commit_group;\n\tcp.async.wait_group 0;" ::: "memory");
}
__device__ __forceinline__ unsigned int fmap(float f) {
    const unsigned int u = __float_as_uint(f);
    return (u & 0x80000000u) ? ~u : (u | 0x80000000u);
}
__device__ __forceinline__ float funmap(unsigned int m) {
    return (m & 0x80000000u) ? __uint_as_float(m & 0x7FFFFFFFu)
                             : __uint_as_float(~m);
}
__device__ __forceinline__ float dot4(const float a[4], float4 w) {
    float r = a[0] * w.x; r = fmaf(a[1], w.y, r);
    r = fmaf(a[2], w.z, r); return fmaf(a[3], w.w, r);
}

__global__ __launch_bounds__(256, 5) void swise_main_kernel(
    const int* __restrict__ queries, const int* __restrict__ these_queries,
    const float* __restrict__ entity, const float* __restrict__ rel,
    const float* __restrict__ rel_diag,
    const float* __restrict__ bh, const float* __restrict__ bt,
    const float* __restrict__ c_param,
    const float* __restrict__ cnn_w, const float* __restrict__ cnn_b,
    const float* __restrict__ h2e_w, const float* __restrict__ h2e_b,
    const float* __restrict__ cnnn_w, const float* __restrict__ cnnn_b,
    const float* __restrict__ h2en_w, const float* __restrict__ h2en_b,
    const float* __restrict__ noise, float* __restrict__ y_out, int loss_idx)
{
    __shared__ __align__(16) float sx[WPB][XSZ];   // x image per warp
    __shared__ float2 swcn[25];                    // interleaved conv weights
    __shared__ float sbc[2];
    __shared__ float sbeb[18];                     // [0..8]=h2e_b, [9..17]=h2en_b
    __shared__ float s_load[EE], s_imp[EE];
    __shared__ unsigned int s_is_last;
    __shared__ double totals[18];

    const int tid = threadIdx.x;
    for (int i = tid; i < 25; i += blockDim.x)
        swcn[i] = make_float2(cnn_w[i], cnnn_w[i]);
    if (tid == 0) { sbc[0] = cnn_b[0]; sbc[1] = cnnn_b[0]; }
    if (tid < EE) { sbeb[tid] = h2e_b[tid]; sbeb[9 + tid] = h2en_b[tid];
                    s_load[tid] = 0.0f; s_imp[tid] = 0.0f; }
    __syncthreads();

    const int warp = tid >> 5, lane = tid & 31;
    const int ly = lane >> 2;
    const int lx = lane & 3;
    const int f4 = (16 * ly + 4 * lx) >> 2;
    const bool lowh = (lane < 16);
    const bool isA = (lane < EE);
    const bool isB = (lane >= 16) && (lane < 16 + EE);
    const int eIdx = isB ? (lane - 16) : lane;
    float* sxw = sx[warp];
    const unsigned int sxw_u32 =
        (unsigned int)__cvta_generic_to_shared(sxw);
    const float4* wc4p = (const float4*)h2e_w;
    const float4* wn4p = (const float4*)h2en_w;
    const int gw = blockIdx.x * WPB + warp;

    // ---- pre-stage first pair's element A (head + rel) ----
    {
        const int b0 = 2 * gw;
        const float2* hrow = (const float2*)(entity + (size_t)queries[3 * b0] * DD);
        const float4* rrow = (const float4*)(rel + (size_t)queries[3 * b0 + 1] * (2 * DD));
        #pragma unroll
        for (int t = 0; t < 7; t++) {
            const int i = lane + 32 * t;
            cp_async8(sxw_u32 + 4 * (XOFF + 2 * i), hrow + i);
            cp_async16(sxw_u32 + 4 * (XOFF + DD + 4 * i), rrow + i);
        }
        if (lane == 0) {
            cp_async8(sxw_u32 + 4 * (XOFF + 2 * 224), hrow + 224);
            cp_async16(sxw_u32 + 4 * (XOFF + DD + 4 * 224), rrow + 224);
        }
    }

    for (int pb = gw; pb < BB / 2; pb += TOTW) {
        const int bA = 2 * pb, bB = 2 * pb + 1;
        const int q0A = queries[3 * bA], q1A = queries[3 * bA + 1];
        const int t2A = these_queries[3 * bA + 2];
        const int q0B = queries[3 * bB], q1B = queries[3 * bB + 1];
        const int t2B = these_queries[3 * bB + 2];

        // noise: lane e<9 -> element A expert e; lane 16+e -> element B expert e
        float noi = 0.0f;
        if (isA)      noi = __ldg(noise + (size_t)bA * EE + lane);
        else if (isB) noi = __ldg(noise + (size_t)bB * EE + (lane - 16));

        // ---- wait for pre-staged A ----
        cp_async_wait_all();
        __syncwarp();

        // ---- conv A ----
        float accAc[4] = {0.f, 0.f, 0.f, 0.f};
        float accAn[4] = {0.f, 0.f, 0.f, 0.f};
        #pragma unroll
        for (int kh = 0; kh < 5; kh++) {
            const float* rp = sxw + XOFF + (3 * ly + kh) * RANKK + 12 * lx;
            float row[14];
            #pragma unroll
            for (int j2 = 0; j2 < 7; j2++) {
                const float2 t = *(const float2*)(rp + 2 * j2);
                row[2 * j2] = t.x; row[2 * j2 + 1] = t.y;
            }
            #pragma unroll
            for (int kw = 0; kw < 5; kw++) {
                const float2 w2 = swcn[kh * 5 + kw];
                #pragma unroll
                for (int q = 0; q < 4; q++) {
                    const float xv = row[3 * q + kw];
                    accAc[q] = fmaf(xv, w2.x, accAc[q]);
                    accAn[q] = fmaf(xv, w2.y, accAn[q]);
                }
            }
        }
        #pragma unroll
        for (int q = 0; q < 4; q++) { accAc[q] += sbc[0]; accAn[q] += sbc[1]; }

        __syncwarp();   // conv A reads done before restaging

        // ---- stage element B (same buffer) ----
        {
            const float2* hrow = (const float2*)(entity + (size_t)q0B * DD);
            const float4* rrow = (const float4*)(rel + (size_t)q1B * (2 * DD));
            #pragma unroll
            for (int t = 0; t < 7; t++) {
                const int i = lane + 32 * t;
                cp_async8(sxw_u32 + 4 * (XOFF + 2 * i), hrow + i);
                cp_async16(sxw_u32 + 4 * (XOFF + DD + 4 * i), rrow + i);
            }
            if (lane == 0) {
                cp_async8(sxw_u32 + 4 * (XOFF + 2 * 224), hrow + 224);
                cp_async16(sxw_u32 + 4 * (XOFF + DD + 4 * 224), rrow + 224);
            }
        }
        cp_async_wait_all();
        __syncwarp();

        // ---- conv B ----
        float accBc[4] = {0.f, 0.f, 0.f, 0.f};
        float accBn[4] = {0.f, 0.f, 0.f, 0.f};
        #pragma unroll
        for (int kh = 0; kh < 5; kh++) {
            const float* rp = sxw + XOFF + (3 * ly + kh) * RANKK + 12 * lx;
            float row[14];
            #pragma unroll
            for (int j2 = 0; j2 < 7; j2++) {
                const float2 t = *(const float2*)(rp + 2 * j2);
                row[2 * j2] = t.x; row[2 * j2 + 1] = t.y;
            }
            #pragma unroll
            for (int kw = 0; kw < 5; kw++) {
                const float2 w2 = swcn[kh * 5 + kw];
                #pragma unroll
                for (int q = 0; q < 4; q++) {
                    const float xv = row[3 * q + kw];
                    accBc[q] = fmaf(xv, w2.x, accBc[q]);
                    accBn[q] = fmaf(xv, w2.y, accBn[q]);
                }
            }
        }
        #pragma unroll
        for (int q = 0; q < 4; q++) { accBc[q] += sbc[0]; accBn[q] += sbc[1]; }

        // ---- joint linear, ROUND-MAJOR reduction ----
        // phase 1: per-expert dot + single-shfl route (u=clean sums, v=noise sums)
        float u[EE], v[EE];
        #pragma unroll
        for (int e = 0; e < EE; e++) {
            const float4 wc4 = __ldg(wc4p + e * 32 + f4);
            const float4 wn4 = __ldg(wn4p + e * 32 + f4);
            const float cA = dot4(accAc, wc4), nA = dot4(accAn, wn4);
            const float cB = dot4(accBc, wc4), nB = dot4(accBn, wn4);
            const float cx = __shfl_xor_sync(0xffffffffu, lowh ? cB : cA, 16);
            const float nx = __shfl_xor_sync(0xffffffffu, lowh ? nB : nA, 16);
            u[e] = (lowh ? cA : cB) + cx;
            v[e] = (lowh ? nA : nB) + nx;
        }
        // phase 2: 4 rounds, each 18 independent shfl (short dependency chain)
        #pragma unroll
        for (int off = 8; off > 0; off >>= 1) {
            #pragma unroll
            for (int e = 0; e < EE; e++) {
                u[e] += __shfl_xor_sync(0xffffffffu, u[e], off);
                v[e] += __shfl_xor_sync(0xffffffffu, v[e], off);
            }
        }
        // phase 3: lane e picks A-expert-e (low) / B-expert-e (lane 16+e)
        float ce = 0.0f, nr = 0.0f;
        #pragma unroll
        for (int e = 0; e < EE; e++)
            if (eIdx == e) { ce = u[e]; nr = v[e]; }

        // ---- gating: A on lanes 0..8, B on lanes 16..24 ----
        float se = 1.0f, ne = 0.0f;
        unsigned int m = 0u;
        if (isA || isB) {
            ce += sbeb[eIdx];
            se = softplusf(nr + sbeb[9 + eIdx]) + 0.01f;
            ne = fmaf(noi, se, ce);
            m = fmap(ne);
        }
        const unsigned int mA = isA ? m : 0u;
        const unsigned int M1A = __reduce_max_sync(0xffffffffu, mA);
        const int i1A = __ffs(__ballot_sync(0xffffffffu, isA && mA == M1A)) - 1;
        const unsigned int mA2 = (lane == i1A) ? 0u : mA;
        const unsigned int M2A = __reduce_max_sync(0xffffffffu, mA2);
        const int i2A = __ffs(__ballot_sync(0xffffffffu, isA && lane != i1A && mA2 == M2A)) - 1;
        const unsigned int mA3 = (lane == i2A) ? 0u : mA2;
        const unsigned int M3A = __reduce_max_sync(0xffffffffu, mA3);
        const float v1A = funmap(M1A), v2A = funmap(M2A), v3A = funmap(M3A);
        const unsigned int mB = isB ? m : 0u;
        const unsigned int M1B = __reduce_max_sync(0xffffffffu, mB);
        const int l1B = __ffs(__ballot_sync(0xffffffffu, isB && mB == M1B)) - 1;
        const unsigned int mB2 = (lane == l1B) ? 0u : mB;
        const unsigned int M2B = __reduce_max_sync(0xffffffffu, mB2);
        const int l2B = __ffs(__ballot_sync(0xffffffffu, isB && lane != l1B && mB2 == M2B)) - 1;
        const unsigned int mB3 = (lane == l2B) ? 0u : mB2;
        const unsigned int M3B = __reduce_max_sync(0xffffffffu, mB3);
        const float v1B = funmap(M1B), v2B = funmap(M2B), v3B = funmap(M3B);
        const int e1B = l1B - 16, e2B = l2B - 16;

        if (isA || isB) {
            const float v3s = isA ? v3A : v3B;
            const float v2s = isA ? v2A : v2B;
            const float thr = (ne > v3s) ? v3s : v2s;
            atomicAdd(&s_load[eIdx], phif((ce - thr) / se));
        }
        const float tA = expf(v2A - v1A);
        const float g1A = 1.0f / (1.0f + tA), g2A = tA / (1.0f + tA);
        const float tB = expf(v2B - v1B);
        const float g1B = 1.0f / (1.0f + tB), g2B = tB / (1.0f + tB);
        if (lane == 0) {
            atomicAdd(&s_imp[i1A], g1A);
            if (g2A > 0.0f) atomicAdd(&s_imp[i2A], g2A);
        }
        if (lane == 1) {
            atomicAdd(&s_imp[e1B], g1B);
            if (g2B > 0.0f) atomicAdd(&s_imp[e2B], g2B);
        }

        // ---- Givens B FIRST: x-values from smem (B image still resident) ----
        {
            const float* rd = rel_diag + (size_t)q1B * DD;
            const float* rh = entity + (size_t)t2B * DD;
            float d1 = 0.0f, d2 = 0.0f;
            {
                const bool sel = lane < 25;
                const int e = sel ? e1B : e2B;
                const int p = sel ? lane : lane - 25;
                const float2 r2 = __ldg((const float2*)(rd + e * RANKK) + p);
                const float2 h2v = __ldg((const float2*)(rh + e * RANKK) + p);
                const float2 x01 = *(const float2*)&sxw[XOFF + e * RANKK + 2 * p];
                const float2 rl01 = *(const float2*)&sxw[XOFF + DD + e * (2 * RANKK) + 2 * p];
                const float inv = rsqrtf(fmaxf(r2.x * r2.x + r2.y * r2.y, 1e-30f));
                const float c0 = r2.x * inv, c1 = r2.y * inv;
                const float u0 = (c0 * x01.x - c1 * x01.y) + rl01.x - h2v.x;
                const float u1 = (c1 * x01.x + c0 * x01.y) + rl01.y - h2v.y;
                const float dd = fmaf(u0, u0, u1 * u1);
                if (sel) d1 += dd; else d2 += dd;
            }
            if (lane < 18) {
                const int p = lane + 7, e = e2B;
                const float2 r2 = __ldg((const float2*)(rd + e * RANKK) + p);
                const float2 h2v = __ldg((const float2*)(rh + e * RANKK) + p);
                const float2 x01 = *(const float2*)&sxw[XOFF + e * RANKK + 2 * p];
                const float2 rl01 = *(const float2*)&sxw[XOFF + DD + e * (2 * RANKK) + 2 * p];
                const float inv = rsqrtf(fmaxf(r2.x * r2.x + r2.y * r2.y, 1e-30f));
                const float c0 = r2.x * inv, c1 = r2.y * inv;
                const float u0 = (c0 * x01.x - c1 * x01.y) + rl01.x - h2v.x;
                const float u1 = (c1 * x01.x + c0 * x01.y) + rl01.y - h2v.y;
                d2 = fmaf(u0, u0, fmaf(u1, u1, d2));
            }
            #pragma unroll
            for (int off = 16; off > 0; off >>= 1) {
                d1 += __shfl_xor_sync(0xffffffffu, d1, off);
                d2 += __shfl_xor_sync(0xffffffffu, d2, off);
            }
            if (lane == 0) {
                const float cc = softplusf(c_param[q1B]);
                const float bsum = bh[q0B] + bt[t2B];
                float s = expf(bsum - cc * d1)
                        + (g2B > 0.0f ? expf(bsum - cc * d2) : 0.0f);
                if (s == 0.0f) s = 2.220446049250313e-16f;
                y_out[bB] = logf(s);
            }
        }

        __syncwarp();   // Givens B reads of sxw complete -> buffer dead

        // ---- pre-stage NEXT pair's element A (hidden behind Givens A) ----
        if (pb + TOTW < BB / 2) {
            const int bn = 2 * (pb + TOTW);
            const float2* hrow = (const float2*)(entity + (size_t)queries[3 * bn] * DD);
            const float4* rrow = (const float4*)(rel + (size_t)queries[3 * bn + 1] * (2 * DD));
            #pragma unroll
            for (int t = 0; t < 7; t++) {
                const int i = lane + 32 * t;
                cp_async8(sxw_u32 + 4 * (XOFF + 2 * i), hrow + i);
                cp_async16(sxw_u32 + 4 * (XOFF + DD + 4 * i), rrow + i);
            }
            if (lane == 0) {
                cp_async8(sxw_u32 + 4 * (XOFF + 2 * 224), hrow + 224);
                cp_async16(sxw_u32 + 4 * (XOFF + DD + 4 * 224), rrow + 224);
            }
        }

        // ---- Givens A: operands from global (L1-hot from staging) ----
        {
            const float* rd = rel_diag + (size_t)q1A * DD;
            const float* rh = entity + (size_t)t2A * DD;
            const float* hx = entity + (size_t)q0A * DD;
            const float* rl = rel + (size_t)q1A * (2 * DD);
            float d1 = 0.0f, d2 = 0.0f;
            {
                const bool sel = lane < 25;
                const int e = sel ? i1A : i2A;
                const int p = sel ? lane : lane - 25;
                const float2 r2 = __ldg((const float2*)(rd + e * RANKK) + p);
                const float2 h2v = __ldg((const float2*)(rh + e * RANKK) + p);
                const float2 x01 = __ldg((const float2*)(hx + e * RANKK) + p);
                const float2 rl01 = __ldg((const float2*)(rl + e * 2 * RANKK) + p);
                const float inv = rsqrtf(fmaxf(r2.x * r2.x + r2.y * r2.y, 1e-30f));
                const float c0 = r2.x * inv, c1 = r2.y * inv;
                const float u0 = (c0 * x01.x - c1 * x01.y) + rl01.x - h2v.x;
                const float u1 = (c1 * x01.x + c0 * x01.y) + rl01.y - h2v.y;
                const float dd = fmaf(u0, u0, u1 * u1);
                if (sel) d1 += dd; else d2 += dd;
            }
            if (lane < 18) {
                const int p = lane + 7, e = i2A;
                const float2 r2 = __ldg((const float2*)(rd + e * RANKK) + p);
                const float2 h2v = __ldg((const float2*)(rh + e * RANKK) + p);
                const float2 x01 = __ldg((const float2*)(hx + e * RANKK) + p);
                const float2 rl01 = __ldg((const float2*)(rl + e * 2 * RANKK) + p);
                const float inv = rsqrtf(fmaxf(r2.x * r2.x + r2.y * r2.y, 1e-30f));
                const float c0 = r2.x * inv, c1 = r2.y * inv;
                const float u0 = (c0 * x01.x - c1 * x01.y) + rl01.x - h2v.x;
                const float u1 = (c1 * x01.x + c0 * x01.y) + rl01.y - h2v.y;
                d2 = fmaf(u0, u0, fmaf(u1, u1, d2));
            }
            #pragma unroll
            for (int off = 16; off > 0; off >>= 1) {
                d1 += __shfl_xor_sync(0xffffffffu, d1, off);
                d2 += __shfl_xor_sync(0xffffffffu, d2, off);
            }
            if (lane == 0) {
                const float cc = softplusf(c_param[q1A]);
                const float bsum = bh[q0A] + bt[t2A];
                float s = expf(bsum - cc * d1)
                        + (g2A > 0.0f ? expf(bsum - cc * d2) : 0.0f);
                if (s == 0.0f) s = 2.220446049250313e-16f;
                y_out[bA] = logf(s);
            }
        }
    }

    __syncthreads();
    if (tid < EE)       g_part[tid * NBP + blockIdx.x] = s_load[tid];
    else if (tid < 18)  g_part[tid * NBP + blockIdx.x] = s_imp[tid - 9];
    __threadfence();
    if (tid == 0) {
        const unsigned int c = atomicAdd(&g_count, 1u);
        s_is_last = (c == NB - 1) ? 1u : 0u;
    }
    __syncthreads();
    if (!s_is_last) return;

    for (int v2 = warp; v2 < 18; v2 += WPB) {
        float acc = 0.0f;
        #pragma unroll
        for (int j = 0; j < NBP / 32; j++)
            acc += g_part[v2 * NBP + j * 32 + lane];
        #pragma unroll
        for (int off = 16; off > 0; off >>= 1)
            acc += __shfl_xor_sync(0xffffffffu, acc, off);
        if (lane == 0) totals[v2] = (double)acc;
    }
    __syncthreads();
    if (tid == 0) {
        double ml = 0.0, mi = 0.0;
        for (int e = 0; e < EE; e++) { ml += totals[e]; mi += totals[9 + e]; }
        ml /= (double)EE; mi /= (double)EE;
        double vl = 0.0, vi = 0.0;
        for (int e = 0; e < EE; e++) {
            const double dl = totals[e] - ml;     vl += dl * dl;
            const double di = totals[9 + e] - mi; vi += di * di;
        }
        vl /= (double)(EE - 1); vi /= (double)(EE - 1);
        const double cvl = vl / (ml * ml + 1e-10);
        const double cvi = vi / (mi * mi + 1e-10);
        y_out[loss_idx] = (float)(0.01 * (cvi + cvl));
        g_count = 0;
    }
}

extern "C" void kernel_launch(void* const* d_in, const int* in_sizes, int n_in,
                              void* d_out, int out_size) {
    const int*   queries       = (const int*)  d_in[0];
    const int*   these_queries = (const int*)  d_in[1];
    const float* entity        = (const float*)d_in[2];
    const float* rel           = (const float*)d_in[3];
    const float* rel_diag      = (const float*)d_in[4];
    const float* bh            = (const float*)d_in[5];
    const float* bt            = (const float*)d_in[6];
    const float* c_param       = (const float*)d_in[7];
    const float* cnn_w         = (const float*)d_in[8];
    const float* cnn_b         = (const float*)d_in[9];
    const float* h2e_w         = (const float*)d_in[10];
    const float* h2e_b         = (const float*)d_in[11];
    const float* cnnn_w        = (const float*)d_in[12];
    const float* cnnn_b        = (const float*)d_in[13];
    const float* h2en_w        = (const float*)d_in[14];
    const float* h2en_b        = (const float*)d_in[15];
    const float* noise         = (const float*)d_in[16];
    float* out = (float*)d_out;

    swise_main_kernel<<<NB, 256>>>(
        queries, these_queries, entity, rel, rel_diag, bh, bt, c_param,
        cnn_w, cnn_b, h2e_w, h2e_b, cnnn_w, cnnn_b, h2en_w, h2en_b,
        noise, out, out_size - 1);
}

// round 17
// speedup vs baseline: 1.0832x; 1.0832x over previous
#include <cuda_runtime.h>
#include <math.h>

#define BB 32768
#define EE 9
#define RANKK 50
#define DD 450            // E*RANK
#define WPB 8             // warps per block
#define NB 740            // persistent grid: 148 SMs x 5 blocks
#define NBP 768           // padded partial stride (pad slots stay zero)
#define TOTW (NB * WPB)   // 5920 warps
#define XOFF 2            // head starts at sxw[2] so rel (sxw[452]) is 16B-aligned
#define XSZ 1352          // 2 + 450 + 900

// per-block partials: [v*NBP + block], v = 0..8 load, 9..17 importance
__device__ float g_part[18 * NBP];
__device__ unsigned int g_count = 0;

__device__ __forceinline__ float softplusf(float x) {
    if (x > 20.0f) return x;
    return log1pf(expf(x));
}
__device__ __forceinline__ float phif(float z) {
    return 0.5f * (1.0f + erff(z * 0.70710678118654752f));
}
__device__ __forceinline__ void cp_async8(unsigned int dst, const void* src) {
    asm volatile("cp.async.ca.shared.global [%0], [%1], 8;" :: "r"(dst), "l"(src));
}
__device__ __forceinline__ void cp_async16(unsigned int dst, const void* src) {
    asm volatile("cp.async.ca.shared.global [%0], [%1], 16;" :: "r"(dst), "l"(src));
}
__device__ __forceinline__ void cp_async_wait_all() {
    asm volatile("cp.async.commit_group;\n\tcp.async.wait_group 0;" ::: "memory");
}
__device__ __forceinline__ unsigned int fmap(float f) {
    const unsigned int u = __float_as_uint(f);
    return (u & 0x80000000u) ? ~u : (u | 0x80000000u);
}
__device__ __forceinline__ float funmap(unsigned int m) {
    return (m & 0x80000000u) ? __uint_as_float(m & 0x7FFFFFFFu)
                             : __uint_as_float(~m);
}
__device__ __forceinline__ float dot4(const float a[4], float4 w) {
    float r = a[0] * w.x; r = fmaf(a[1], w.y, r);
    r = fmaf(a[2], w.z, r); return fmaf(a[3], w.w, r);
}

__global__ __launch_bounds__(256, 5) void swise_main_kernel(
    const int* __restrict__ queries, const int* __restrict__ these_queries,
    const float* __restrict__ entity, const float* __restrict__ rel,
    const float* __restrict__ rel_diag,
    const float* __restrict__ bh, const float* __restrict__ bt,
    const float* __restrict__ c_param,
    const float* __restrict__ cnn_w, const float* __restrict__ cnn_b,
    const float* __restrict__ h2e_w, const float* __restrict__ h2e_b,
    const float* __restrict__ cnnn_w, const float* __restrict__ cnnn_b,
    const float* __restrict__ h2en_w, const float* __restrict__ h2en_b,
    const float* __restrict__ noise, float* __restrict__ y_out, int loss_idx)
{
    __shared__ __align__(16) float sx[WPB][XSZ];   // x image per warp
    __shared__ float2 swcn[25];                    // interleaved conv weights
    __shared__ float sbc[2];
    __shared__ float sbeb[18];                     // [0..8]=h2e_b, [9..17]=h2en_b
    __shared__ float s_load[EE], s_imp[EE];
    __shared__ unsigned int s_is_last;
    __shared__ double totals[18];

    const int tid = threadIdx.x;
    for (int i = tid; i < 25; i += blockDim.x)
        swcn[i] = make_float2(cnn_w[i], cnnn_w[i]);
    if (tid == 0) { sbc[0] = cnn_b[0]; sbc[1] = cnnn_b[0]; }
    if (tid < EE) { sbeb[tid] = h2e_b[tid]; sbeb[9 + tid] = h2en_b[tid];
                    s_load[tid] = 0.0f; s_imp[tid] = 0.0f; }
    __syncthreads();

    const int warp = tid >> 5, lane = tid & 31;
    const int ly = lane >> 2;
    const int lx = lane & 3;
    const int f4 = (16 * ly + 4 * lx) >> 2;
    const bool lowh = (lane < 16);
    const bool isA = (lane < EE);
    const bool isB = (lane >= 16) && (lane < 16 + EE);
    const int eIdx = isB ? (lane - 16) : lane;
    float* sxw = sx[warp];
    const unsigned int sxw_u32 =
        (unsigned int)__cvta_generic_to_shared(sxw);
    const float4* wc4p = (const float4*)h2e_w;
    const float4* wn4p = (const float4*)h2en_w;
    const int gw = blockIdx.x * WPB + warp;

    for (int pb = gw; pb < BB / 2; pb += TOTW) {
        const int bA = 2 * pb, bB = 2 * pb + 1;
        const int q0A = queries[3 * bA], q1A = queries[3 * bA + 1];
        const int t2A = these_queries[3 * bA + 2];
        const int q0B = queries[3 * bB], q1B = queries[3 * bB + 1];
        const int t2B = these_queries[3 * bB + 2];

        __syncwarp();   // WAR: previous pair's reads of sxw done

        // ---- stage element A ----
        {
            const float2* hrow = (const float2*)(entity + (size_t)q0A * DD);
            const float4* rrow = (const float4*)(rel + (size_t)q1A * (2 * DD));
            #pragma unroll
            for (int t = 0; t < 7; t++) {
                const int i = lane + 32 * t;
                cp_async8(sxw_u32 + 4 * (XOFF + 2 * i), hrow + i);
                cp_async16(sxw_u32 + 4 * (XOFF + DD + 4 * i), rrow + i);
            }
            if (lane == 0) {
                cp_async8(sxw_u32 + 4 * (XOFF + 2 * 224), hrow + 224);
                cp_async16(sxw_u32 + 4 * (XOFF + DD + 4 * 224), rrow + 224);
            }
        }
        // noise: lane e<9 -> element A expert e; lane 16+e -> element B expert e
        float noi = 0.0f;
        if (isA)      noi = __ldg(noise + (size_t)bA * EE + lane);
        else if (isB) noi = __ldg(noise + (size_t)bB * EE + (lane - 16));
        cp_async_wait_all();
        __syncwarp();

        // ---- conv A (accumulators bias-initialized) ----
        float accAc[4] = {sbc[0], sbc[0], sbc[0], sbc[0]};
        float accAn[4] = {sbc[1], sbc[1], sbc[1], sbc[1]};
        #pragma unroll
        for (int kh = 0; kh < 5; kh++) {
            const float* rp = sxw + XOFF + (3 * ly + kh) * RANKK + 12 * lx;
            float row[14];
            #pragma unroll
            for (int j2 = 0; j2 < 7; j2++) {
                const float2 t = *(const float2*)(rp + 2 * j2);
                row[2 * j2] = t.x; row[2 * j2 + 1] = t.y;
            }
            #pragma unroll
            for (int kw = 0; kw < 5; kw++) {
                const float2 w2 = swcn[kh * 5 + kw];
                #pragma unroll
                for (int q = 0; q < 4; q++) {
                    const float xv = row[3 * q + kw];
                    accAc[q] = fmaf(xv, w2.x, accAc[q]);
                    accAn[q] = fmaf(xv, w2.y, accAn[q]);
                }
            }
        }

        __syncwarp();   // conv A reads done before restaging

        // ---- stage element B (same buffer) ----
        {
            const float2* hrow = (const float2*)(entity + (size_t)q0B * DD);
            const float4* rrow = (const float4*)(rel + (size_t)q1B * (2 * DD));
            #pragma unroll
            for (int t = 0; t < 7; t++) {
                const int i = lane + 32 * t;
                cp_async8(sxw_u32 + 4 * (XOFF + 2 * i), hrow + i);
                cp_async16(sxw_u32 + 4 * (XOFF + DD + 4 * i), rrow + i);
            }
            if (lane == 0) {
                cp_async8(sxw_u32 + 4 * (XOFF + 2 * 224), hrow + 224);
                cp_async16(sxw_u32 + 4 * (XOFF + DD + 4 * 224), rrow + 224);
            }
        }
        cp_async_wait_all();
        __syncwarp();

        // ---- conv B (accumulators bias-initialized) ----
        float accBc[4] = {sbc[0], sbc[0], sbc[0], sbc[0]};
        float accBn[4] = {sbc[1], sbc[1], sbc[1], sbc[1]};
        #pragma unroll
        for (int kh = 0; kh < 5; kh++) {
            const float* rp = sxw + XOFF + (3 * ly + kh) * RANKK + 12 * lx;
            float row[14];
            #pragma unroll
            for (int j2 = 0; j2 < 7; j2++) {
                const float2 t = *(const float2*)(rp + 2 * j2);
                row[2 * j2] = t.x; row[2 * j2 + 1] = t.y;
            }
            #pragma unroll
            for (int kw = 0; kw < 5; kw++) {
                const float2 w2 = swcn[kh * 5 + kw];
                #pragma unroll
                for (int q = 0; q < 4; q++) {
                    const float xv = row[3 * q + kw];
                    accBc[q] = fmaf(xv, w2.x, accBc[q]);
                    accBn[q] = fmaf(xv, w2.y, accBn[q]);
                }
            }
        }

        // ---- joint linear: expert-major, 2-shfl route (register-neutral) ----
        float ce = 0.0f, nr = 0.0f;   // lane e<9: A's; lane 16+e: B's
        #pragma unroll
        for (int e = 0; e < EE; e++) {
            const float4 wc4 = __ldg(wc4p + e * 32 + f4);
            const float4 wn4 = __ldg(wn4p + e * 32 + f4);
            const float cA = dot4(accAc, wc4), nA = dot4(accAn, wn4);
            const float cB = dot4(accBc, wc4), nB = dot4(accBn, wn4);
            // each lane ships the value its cross-half partner needs
            const float cx = __shfl_xor_sync(0xffffffffu, lowh ? cB : cA, 16);
            const float nx = __shfl_xor_sync(0xffffffffu, lowh ? nB : nA, 16);
            float u = (lowh ? cA : cB) + cx;
            float v = (lowh ? nA : nB) + nx;
            #pragma unroll
            for (int off = 8; off > 0; off >>= 1) {
                u += __shfl_xor_sync(0xffffffffu, u, off);
                v += __shfl_xor_sync(0xffffffffu, v, off);
            }
            if (lane == e)      { ce = u; nr = v; }
            if (lane == 16 + e) { ce = u; nr = v; }
        }

        // ---- gating: A on lanes 0..8, B on lanes 16..24 ----
        float se = 1.0f, ne = 0.0f;
        unsigned int m = 0u;
        if (isA || isB) {
            ce += sbeb[eIdx];
            se = softplusf(nr + sbeb[9 + eIdx]) + 0.01f;
            ne = fmaf(noi, se, ce);
            m = fmap(ne);
        }
        const unsigned int mA = isA ? m : 0u;
        const unsigned int M1A = __reduce_max_sync(0xffffffffu, mA);
        const int i1A = __ffs(__ballot_sync(0xffffffffu, isA && mA == M1A)) - 1;
        const unsigned int mA2 = (lane == i1A) ? 0u : mA;
        const unsigned int M2A = __reduce_max_sync(0xffffffffu, mA2);
        const int i2A = __ffs(__ballot_sync(0xffffffffu, isA && lane != i1A && mA2 == M2A)) - 1;
        const unsigned int mA3 = (lane == i2A) ? 0u : mA2;
        const unsigned int M3A = __reduce_max_sync(0xffffffffu, mA3);
        const float v1A = funmap(M1A), v2A = funmap(M2A), v3A = funmap(M3A);
        const unsigned int mB = isB ? m : 0u;
        const unsigned int M1B = __reduce_max_sync(0xffffffffu, mB);
        const int l1B = __ffs(__ballot_sync(0xffffffffu, isB && mB == M1B)) - 1;
        const unsigned int mB2 = (lane == l1B) ? 0u : mB;
        const unsigned int M2B = __reduce_max_sync(0xffffffffu, mB2);
        const int l2B = __ffs(__ballot_sync(0xffffffffu, isB && lane != l1B && mB2 == M2B)) - 1;
        const unsigned int mB3 = (lane == l2B) ? 0u : mB2;
        const unsigned int M3B = __reduce_max_sync(0xffffffffu, mB3);
        const float v1B = funmap(M1B), v2B = funmap(M2B), v3B = funmap(M3B);
        const int e1B = l1B - 16, e2B = l2B - 16;

        if (isA || isB) {
            const float v3s = isA ? v3A : v3B;
            const float v2s = isA ? v2A : v2B;
            const float thr = (ne > v3s) ? v3s : v2s;
            atomicAdd(&s_load[eIdx], phif((ce - thr) / se));
        }
        const float tA = expf(v2A - v1A);
        const float g1A = 1.0f / (1.0f + tA), g2A = tA / (1.0f + tA);
        const float tB = expf(v2B - v1B);
        const float g1B = 1.0f / (1.0f + tB), g2B = tB / (1.0f + tB);
        if (lane == 0) {
            atomicAdd(&s_imp[i1A], g1A);
            if (g2A > 0.0f) atomicAdd(&s_imp[i2A], g2A);
        }
        if (lane == 1) {
            atomicAdd(&s_imp[e1B], g1B);
            if (g2B > 0.0f) atomicAdd(&s_imp[e2B], g2B);
        }

        // ---- Givens A: x-values from GLOBAL (sx now holds B) ----
        {
            const float* rd = rel_diag + (size_t)q1A * DD;
            const float* rh = entity + (size_t)t2A * DD;
            const float* hx = entity + (size_t)q0A * DD;
            const float* rl = rel + (size_t)q1A * (2 * DD);
            float d1 = 0.0f, d2 = 0.0f;
            {
                const bool sel = lane < 25;
                const int e = sel ? i1A : i2A;
                const int p = sel ? lane : lane - 25;
                const float2 r2 = __ldg((const float2*)(rd + e * RANKK) + p);
                const float2 h2v = __ldg((const float2*)(rh + e * RANKK) + p);
                const float2 x01 = __ldg((const float2*)(hx + e * RANKK) + p);
                const float2 rl01 = __ldg((const float2*)(rl + e * 2 * RANKK) + p);
                const float inv = rsqrtf(fmaxf(r2.x * r2.x + r2.y * r2.y, 1e-30f));
                const float c0 = r2.x * inv, c1 = r2.y * inv;
                const float u0 = (c0 * x01.x - c1 * x01.y) + rl01.x - h2v.x;
                const float u1 = (c1 * x01.x + c0 * x01.y) + rl01.y - h2v.y;
                const float dd = fmaf(u0, u0, u1 * u1);
                if (sel) d1 += dd; else d2 += dd;
            }
            if (lane < 18) {
                const int p = lane + 7, e = i2A;
                const float2 r2 = __ldg((const float2*)(rd + e * RANKK) + p);
                const float2 h2v = __ldg((const float2*)(rh + e * RANKK) + p);
                const float2 x01 = __ldg((const float2*)(hx + e * RANKK) + p);
                const float2 rl01 = __ldg((const float2*)(rl + e * 2 * RANKK) + p);
                const float inv = rsqrtf(fmaxf(r2.x * r2.x + r2.y * r2.y, 1e-30f));
                const float c0 = r2.x * inv, c1 = r2.y * inv;
                const float u0 = (c0 * x01.x - c1 * x01.y) + rl01.x - h2v.x;
                const float u1 = (c1 * x01.x + c0 * x01.y) + rl01.y - h2v.y;
                d2 = fmaf(u0, u0, fmaf(u1, u1, d2));
            }
            #pragma unroll
            for (int off = 16; off > 0; off >>= 1) {
                d1 += __shfl_xor_sync(0xffffffffu, d1, off);
                d2 += __shfl_xor_sync(0xffffffffu, d2, off);
            }
            if (lane == 0) {
                const float cc = softplusf(c_param[q1A]);
                const float bsum = bh[q0A] + bt[t2A];
                float s = expf(bsum - cc * d1)
                        + (g2A > 0.0f ? expf(bsum - cc * d2) : 0.0f);
                if (s == 0.0f) s = 2.220446049250313e-16f;
                y_out[bA] = logf(s);
            }
        }

        // ---- Givens B: x-values from smem (B image resident) ----
        {
            const float* rd = rel_diag + (size_t)q1B * DD;
            const float* rh = entity + (size_t)t2B * DD;
            float d1 = 0.0f, d2 = 0.0f;
            {
                const bool sel = lane < 25;
                const int e = sel ? e1B : e2B;
                const int p = sel ? lane : lane - 25;
                const float2 r2 = __ldg((const float2*)(rd + e * RANKK) + p);
                const float2 h2v = __ldg((const float2*)(rh + e * RANKK) + p);
                const float2 x01 = *(const float2*)&sxw[XOFF + e * RANKK + 2 * p];
                const float2 rl01 = *(const float2*)&sxw[XOFF + DD + e * (2 * RANKK) + 2 * p];
                const float inv = rsqrtf(fmaxf(r2.x * r2.x + r2.y * r2.y, 1e-30f));
                const float c0 = r2.x * inv, c1 = r2.y * inv;
                const float u0 = (c0 * x01.x - c1 * x01.y) + rl01.x - h2v.x;
                const float u1 = (c1 * x01.x + c0 * x01.y) + rl01.y - h2v.y;
                const float dd = fmaf(u0, u0, u1 * u1);
                if (sel) d1 += dd; else d2 += dd;
            }
            if (lane < 18) {
                const int p = lane + 7, e = e2B;
                const float2 r2 = __ldg((const float2*)(rd + e * RANKK) + p);
                const float2 h2v = __ldg((const float2*)(rh + e * RANKK) + p);
                const float2 x01 = *(const float2*)&sxw[XOFF + e * RANKK + 2 * p];
                const float2 rl01 = *(const float2*)&sxw[XOFF + DD + e * (2 * RANKK) + 2 * p];
                const float inv = rsqrtf(fmaxf(r2.x * r2.x + r2.y * r2.y, 1e-30f));
                const float c0 = r2.x * inv, c1 = r2.y * inv;
                const float u0 = (c0 * x01.x - c1 * x01.y) + rl01.x - h2v.x;
                const float u1 = (c1 * x01.x + c0 * x01.y) + rl01.y - h2v.y;
                d2 = fmaf(u0, u0, fmaf(u1, u1, d2));
            }
            #pragma unroll
            for (int off = 16; off > 0; off >>= 1) {
                d1 += __shfl_xor_sync(0xffffffffu, d1, off);
                d2 += __shfl_xor_sync(0xffffffffu, d2, off);
            }
            if (lane == 0) {
                const float cc = softplusf(c_param[q1B]);
                const float bsum = bh[q0B] + bt[t2B];
                float s = expf(bsum - cc * d1)
                        + (g2B > 0.0f ? expf(bsum - cc * d2) : 0.0f);
                if (s == 0.0f) s = 2.220446049250313e-16f;
                y_out[bB] = logf(s);
            }
        }
    }

    __syncthreads();
    if (tid < EE)       g_part[tid * NBP + blockIdx.x] = s_load[tid];
    else if (tid < 18)  g_part[tid * NBP + blockIdx.x] = s_imp[tid - 9];
    __threadfence();
    if (tid == 0) {
        const unsigned int c = atomicAdd(&g_count, 1u);
        s_is_last = (c == NB - 1) ? 1u : 0u;
    }
    __syncthreads();
    if (!s_is_last) return;

    for (int v = warp; v < 18; v += WPB) {
        float acc = 0.0f;
        #pragma unroll
        for (int j = 0; j < NBP / 32; j++)
            acc += g_part[v * NBP + j * 32 + lane];
        #pragma unroll
        for (int off = 16; off > 0; off >>= 1)
            acc += __shfl_xor_sync(0xffffffffu, acc, off);
        if (lane == 0) totals[v] = (double)acc;
    }
    __syncthreads();
    if (tid == 0) {
        double ml = 0.0, mi = 0.0;
        for (int e = 0; e < EE; e++) { ml += totals[e]; mi += totals[9 + e]; }
        ml /= (double)EE; mi /= (double)EE;
        double vl = 0.0, vi = 0.0;
        for (int e = 0; e < EE; e++) {
            const double dl = totals[e] - ml;     vl += dl * dl;
            const double di = totals[9 + e] - mi; vi += di * di;
        }
        vl /= (double)(EE - 1); vi /= (double)(EE - 1);
        const double cvl = vl / (ml * ml + 1e-10);
        const double cvi = vi / (mi * mi + 1e-10);
        y_out[loss_idx] = (float)(0.01 * (cvi + cvl));
        g_count = 0;
    }
}

extern "C" void kernel_launch(void* const* d_in, const int* in_sizes, int n_in,
                              void* d_out, int out_size) {
    const int*   queries       = (const int*)  d_in[0];
    const int*   these_queries = (const int*)  d_in[1];
    const float* entity        = (const float*)d_in[2];
    const float* rel           = (const float*)d_in[3];
    const float* rel_diag      = (const float*)d_in[4];
    const float* bh            = (const float*)d_in[5];
    const float* bt            = (const float*)d_in[6];
    const float* c_param       = (const float*)d_in[7];
    const float* cnn_w         = (const float*)d_in[8];
    const float* cnn_b         = (const float*)d_in[9];
    const float* h2e_w         = (const float*)d_in[10];
    const float* h2e_b         = (const float*)d_in[11];
    const float* cnnn_w        = (const float*)d_in[12];
    const float* cnnn_b        = (const float*)d_in[13];
    const float* h2en_w        = (const float*)d_in[14];
    const float* h2en_b        = (const float*)d_in[15];
    const float* noise         = (const float*)d_in[16];
    float* out = (float*)d_out;

    swise_main_kernel<<<NB, 256>>>(
        queries, these_queries, entity, rel, rel_diag, bh, bt, c_param,
        cnn_w, cnn_b, h2e_w, h2e_b, cnnn_w, cnnn_b, h2en_w, h2en_b,
        noise, out, out_size - 1);
}